// round 4
// baseline (speedup 1.0000x reference)
#include <cuda_runtime.h>
#include <cuda_bf16.h>
#include <cstdint>

// Problem constants (fixed by the dataset)
constexpr int B  = 8;
constexpr int NN = 10000;
constexpr int E  = 160000;
constexpr int F  = 128;   // GCN feature dim
constexpr int H  = 256;   // hidden dim
constexpr int BNN = B * NN;          // 80000 rows
constexpr float NEG_SLOPE = 0.01f;

// Scratch (allocation-free: __device__ globals)
__device__ float g_dinv[BNN];
__device__ float g_xw [(size_t)BNN * F];
__device__ float g_agg[(size_t)BNN * F];
__device__ float g_h1 [(size_t)BNN * H];

// ---------------------------------------------------------------------------
// Degree kernels
// ---------------------------------------------------------------------------
__global__ void init_deg_kernel() {
    int i = blockIdx.x * blockDim.x + threadIdx.x;
    if (i < BNN) g_dinv[i] = 1.0f;   // self loop
}

__global__ void count_deg_kernel(const int* __restrict__ ei) {
    int i = blockIdx.x * blockDim.x + threadIdx.x;
    if (i >= B * E) return;
    int b = i / E;
    int e = i - b * E;
    int dst = ei[b * 2 * E + E + e];
    atomicAdd(&g_dinv[b * NN + dst], 1.0f);
}

__global__ void rsqrt_deg_kernel() {
    int i = blockIdx.x * blockDim.x + threadIdx.x;
    if (i < BNN) g_dinv[i] = rsqrtf(g_dinv[i]);
}

// ---------------------------------------------------------------------------
// TF32 tensor-core GEMM: C[M,N] = act(A[M,K] @ Bm[K,N] + bias)
// Block tile 128x128x32, 8 warps (2 x 4), warp tile 64x32, mma m16n8k8.
// ---------------------------------------------------------------------------
constexpr int BM = 128, BN = 128, BK = 32;

__device__ __forceinline__ uint32_t f2tf32(float f) {
    uint32_t r;
    asm("cvt.rna.tf32.f32 %0, %1;" : "=r"(r) : "f"(f));
    return r;
}

__device__ __forceinline__ void mma_tf32(float c[4], uint32_t a0, uint32_t a1,
                                         uint32_t a2, uint32_t a3,
                                         uint32_t b0, uint32_t b1) {
    asm volatile(
        "mma.sync.aligned.m16n8k8.row.col.f32.tf32.tf32.f32 "
        "{%0,%1,%2,%3}, {%4,%5,%6,%7}, {%8,%9}, {%0,%1,%2,%3};"
        : "+f"(c[0]), "+f"(c[1]), "+f"(c[2]), "+f"(c[3])
        : "r"(a0), "r"(a1), "r"(a2), "r"(a3), "r"(b0), "r"(b1));
}

template <int ACT>  // 0 = none, 1 = leaky_relu
__global__ __launch_bounds__(256)
void tf32_gemm_kernel(const float* __restrict__ A, const float* __restrict__ Bm,
                      const float* __restrict__ bias, float* __restrict__ C,
                      int M, int Nn, int K) {
    __shared__ uint32_t As[BK][BM + 1];   // [k][m], pad -> conflict-free
    __shared__ uint32_t Bs[BK][BN + 4];   // [k][n]

    const int tid  = threadIdx.x;
    const int lane = tid & 31;
    const int wid  = tid >> 5;
    const int wm   = wid & 1;   // 2 warps along M
    const int wn   = wid >> 1;  // 4 warps along N

    const int bx = blockIdx.x, by = blockIdx.y;
    const float* Ablk = A + (long long)by * BM * K;
    const float* Bblk = Bm + bx * BN;

    float acc[4][4][4];   // [m_tile][n_tile][frag]
    #pragma unroll
    for (int i = 0; i < 4; i++)
        #pragma unroll
        for (int j = 0; j < 4; j++)
            #pragma unroll
            for (int q = 0; q < 4; q++) acc[i][j][q] = 0.0f;

    // A load mapping: 128 rows x 8 float4 (=32 k) ; 256 threads -> 4 rows each
    const int aR  = tid >> 3;         // 0..31 (base row)
    const int aC4 = tid & 7;          // float4 index along k
    // B load mapping: 8 rows x 32 float4 per pass; 4 passes
    const int bR  = tid >> 5;         // 0..7
    const int bC4 = tid & 31;

    for (int kt = 0; kt < K; kt += BK) {
        #pragma unroll
        for (int r = 0; r < 4; r++) {
            int row = aR + r * 32;
            float4 v = *(const float4*)(Ablk + (long long)row * K + kt + aC4 * 4);
            As[aC4 * 4 + 0][row] = f2tf32(v.x);
            As[aC4 * 4 + 1][row] = f2tf32(v.y);
            As[aC4 * 4 + 2][row] = f2tf32(v.z);
            As[aC4 * 4 + 3][row] = f2tf32(v.w);
        }
        #pragma unroll
        for (int r = 0; r < 4; r++) {
            int row = bR + r * 8;
            float4 v = *(const float4*)(Bblk + (long long)(kt + row) * Nn + bC4 * 4);
            Bs[row][bC4 * 4 + 0] = f2tf32(v.x);
            Bs[row][bC4 * 4 + 1] = f2tf32(v.y);
            Bs[row][bC4 * 4 + 2] = f2tf32(v.z);
            Bs[row][bC4 * 4 + 3] = f2tf32(v.w);
        }
        __syncthreads();

        #pragma unroll
        for (int ks = 0; ks < BK; ks += 8) {
            uint32_t af[4][4];   // [m_tile][reg]
            uint32_t bf[4][2];   // [n_tile][reg]
            #pragma unroll
            for (int i = 0; i < 4; i++) {
                int mrow = wm * 64 + i * 16 + (lane >> 2);
                af[i][0] = As[ks + (lane & 3)    ][mrow];
                af[i][1] = As[ks + (lane & 3)    ][mrow + 8];
                af[i][2] = As[ks + (lane & 3) + 4][mrow];
                af[i][3] = As[ks + (lane & 3) + 4][mrow + 8];
            }
            #pragma unroll
            for (int j = 0; j < 4; j++) {
                int ncol = wn * 32 + j * 8 + (lane >> 2);
                bf[j][0] = Bs[ks + (lane & 3)    ][ncol];
                bf[j][1] = Bs[ks + (lane & 3) + 4][ncol];
            }
            #pragma unroll
            for (int i = 0; i < 4; i++)
                #pragma unroll
                for (int j = 0; j < 4; j++)
                    mma_tf32(acc[i][j], af[i][0], af[i][1], af[i][2], af[i][3],
                             bf[j][0], bf[j][1]);
        }
        __syncthreads();
    }

    // Epilogue: c frag -> rows (lane>>2)+{0,8}, cols 2*(lane&3)+{0,1}
    float* Cblk = C + (long long)by * BM * Nn + bx * BN;
    #pragma unroll
    for (int i = 0; i < 4; i++) {
        #pragma unroll
        for (int j = 0; j < 4; j++) {
            int col = wn * 32 + j * 8 + 2 * (lane & 3);
            float bx0 = 0.0f, bx1 = 0.0f;
            if (bias) { bx0 = bias[bx * BN + col]; bx1 = bias[bx * BN + col + 1]; }
            #pragma unroll
            for (int h = 0; h < 2; h++) {
                int row = wm * 64 + i * 16 + (lane >> 2) + h * 8;
                float2 v;
                v.x = acc[i][j][h * 2 + 0] + bx0;
                v.y = acc[i][j][h * 2 + 1] + bx1;
                if (ACT == 1) {
                    v.x = v.x > 0.0f ? v.x : NEG_SLOPE * v.x;
                    v.y = v.y > 0.0f ? v.y : NEG_SLOPE * v.y;
                }
                *(float2*)(Cblk + (long long)row * Nn + col) = v;
            }
        }
    }
}

// ---------------------------------------------------------------------------
// Self-loop init: agg[n,:] = dinv[n]^2 * xw[n,:]
// ---------------------------------------------------------------------------
__global__ void selfloop_kernel() {
    int i = blockIdx.x * blockDim.x + threadIdx.x;
    if (i >= BNN * (F / 4)) return;
    int row = i / (F / 4);
    float d = g_dinv[row];
    float s = d * d;
    float4 v = ((const float4*)g_xw)[i];
    float4 o;
    o.x = s * v.x; o.y = s * v.y; o.z = s * v.z; o.w = s * v.w;
    ((float4*)g_agg)[i] = o;
}

// ---------------------------------------------------------------------------
// Edge scatter: one warp per edge, scalar atomicAdd (REDG.ADD.F32)
// ---------------------------------------------------------------------------
__global__ __launch_bounds__(256)
void scatter_kernel(const int* __restrict__ ei) {
    int gw = (blockIdx.x * blockDim.x + threadIdx.x) >> 5;
    int lane = threadIdx.x & 31;
    if (gw >= B * E) return;
    int b = gw / E;
    int e = gw - b * E;
    const int* eb = ei + b * 2 * E;
    int src = eb[e];
    int dst = eb[E + e];
    float norm = g_dinv[b * NN + src] * g_dinv[b * NN + dst];
    const float4* s = (const float4*)(g_xw + (long long)(b * NN + src) * F);
    float4 v = s[lane];
    float* d = g_agg + (long long)(b * NN + dst) * F + lane * 4;
    atomicAdd(d + 0, v.x * norm);
    atomicAdd(d + 1, v.y * norm);
    atomicAdd(d + 2, v.z * norm);
    atomicAdd(d + 3, v.w * norm);
}

// ---------------------------------------------------------------------------
// Post: out1 = relu(agg + bc) + x0   (written into g_xw, reused)
// ---------------------------------------------------------------------------
__global__ void post_kernel(const float* __restrict__ x0, const float* __restrict__ bc) {
    int i = blockIdx.x * blockDim.x + threadIdx.x;
    if (i >= BNN * (F / 4)) return;
    int c4 = i & (F / 4 - 1);
    float4 a = ((const float4*)g_agg)[i];
    float4 bb = ((const float4*)bc)[c4];
    float4 x = ((const float4*)x0)[i];
    float4 o;
    o.x = fmaxf(a.x + bb.x, 0.0f) + x.x;
    o.y = fmaxf(a.y + bb.y, 0.0f) + x.y;
    o.z = fmaxf(a.z + bb.z, 0.0f) + x.z;
    o.w = fmaxf(a.w + bb.w, 0.0f) + x.w;
    ((float4*)g_xw)[i] = o;
}

// ---------------------------------------------------------------------------
extern "C" void kernel_launch(void* const* d_in, const int* in_sizes, int n_in,
                              void* d_out, int out_size) {
    const float* x0 = (const float*)d_in[0];       // [B,N,F]
    const int*   ei = (const int*)d_in[1];         // [B,2,E] int32
    const float* Wc = (const float*)d_in[2];       // [F,F]
    const float* bc = (const float*)d_in[3];       // [F]
    const float* W1 = (const float*)d_in[4];       // [F,H]
    const float* b1 = (const float*)d_in[5];       // [H]
    const float* W2 = (const float*)d_in[6];       // [H,H]
    const float* b2 = (const float*)d_in[7];       // [H]
    float* out = (float*)d_out;                    // [B,N,H]

    float *xw, *agg, *h1;
    cudaGetSymbolAddress((void**)&xw,  g_xw);
    cudaGetSymbolAddress((void**)&agg, g_agg);
    cudaGetSymbolAddress((void**)&h1,  g_h1);

    // 1) degrees -> dinv
    init_deg_kernel<<<(BNN + 255) / 256, 256>>>();
    count_deg_kernel<<<(B * E + 255) / 256, 256>>>(ei);
    rsqrt_deg_kernel<<<(BNN + 255) / 256, 256>>>();

    // 2) xw = x0 @ Wc   (M=80000, N=128, K=128)
    {
        dim3 grid(F / BN, BNN / BM);
        tf32_gemm_kernel<0><<<grid, 256>>>(x0, Wc, nullptr, xw, BNN, F, F);
    }

    // 3) agg init with self loop, then edge scatter
    selfloop_kernel<<<(BNN * (F / 4) + 255) / 256, 256>>>();
    scatter_kernel<<<(B * E * 32 + 255) / 256, 256>>>(ei);

    // 4) out1 = relu(agg + bc) + x0  (into g_xw)
    post_kernel<<<(BNN * (F / 4) + 255) / 256, 256>>>(x0, bc);

    // 5) h1 = leaky_relu(out1 @ W1 + b1)  (M=80000, N=256, K=128)
    {
        dim3 grid(H / BN, BNN / BM);
        tf32_gemm_kernel<1><<<grid, 256>>>(xw, W1, b1, h1, BNN, H, F);
    }

    // 6) out = leaky_relu(h1 @ W2 + b2)  (M=80000, N=256, K=256)
    {
        dim3 grid(H / BN, BNN / BM);
        tf32_gemm_kernel<1><<<grid, 256>>>(h1, W2, b2, out, BNN, H, H);
    }
}

// round 5
// speedup vs baseline: 2.2049x; 2.2049x over previous
#include <cuda_runtime.h>
#include <cuda_bf16.h>
#include <cstdint>

// Problem constants (fixed by the dataset)
constexpr int B  = 8;
constexpr int NN = 10000;
constexpr int E  = 160000;
constexpr int F  = 128;   // GCN feature dim
constexpr int H  = 256;   // hidden dim
constexpr int BNN = B * NN;          // 80000 rows
constexpr float NEG_SLOPE = 0.01f;

// Scratch (allocation-free: __device__ globals)
__device__ float g_dinv[BNN];
__device__ float g_xw [(size_t)BNN * F];
__device__ float g_agg[(size_t)BNN * F];
__device__ float g_h1 [(size_t)BNN * H];

// ---------------------------------------------------------------------------
// Degree kernels
// ---------------------------------------------------------------------------
__global__ void init_deg_kernel() {
    int i = blockIdx.x * blockDim.x + threadIdx.x;
    if (i < BNN) g_dinv[i] = 1.0f;   // self loop
}

__global__ void count_deg_kernel(const int* __restrict__ ei) {
    int i = blockIdx.x * blockDim.x + threadIdx.x;
    if (i >= B * E) return;
    int b = i / E;
    int e = i - b * E;
    int dst = ei[b * 2 * E + E + e];
    atomicAdd(&g_dinv[b * NN + dst], 1.0f);
}

__global__ void rsqrt_deg_kernel() {
    int i = blockIdx.x * blockDim.x + threadIdx.x;
    if (i < BNN) g_dinv[i] = rsqrtf(g_dinv[i]);
}

// ---------------------------------------------------------------------------
// TF32 tensor-core GEMM with register prefetch.
// Block tile 128x128x32, 8 warps (2 x 4), warp tile 64x32, mma m16n8k8.
// ---------------------------------------------------------------------------
constexpr int BM = 128, BN = 128, BK = 32;

__device__ __forceinline__ uint32_t f2tf32(float f) {
    uint32_t r;
    asm("cvt.rna.tf32.f32 %0, %1;" : "=r"(r) : "f"(f));
    return r;
}

__device__ __forceinline__ void mma_tf32(float c[4], uint32_t a0, uint32_t a1,
                                         uint32_t a2, uint32_t a3,
                                         uint32_t b0, uint32_t b1) {
    asm volatile(
        "mma.sync.aligned.m16n8k8.row.col.f32.tf32.tf32.f32 "
        "{%0,%1,%2,%3}, {%4,%5,%6,%7}, {%8,%9}, {%0,%1,%2,%3};"
        : "+f"(c[0]), "+f"(c[1]), "+f"(c[2]), "+f"(c[3])
        : "r"(a0), "r"(a1), "r"(a2), "r"(a3), "r"(b0), "r"(b1));
}

template <int ACT>  // 0 = none, 1 = leaky_relu
__global__ __launch_bounds__(256)
void tf32_gemm_kernel(const float* __restrict__ A, const float* __restrict__ Bm,
                      const float* __restrict__ bias, float* __restrict__ C,
                      int M, int Nn, int K) {
    __shared__ uint32_t As[BK][BM + 1];   // [k][m]
    __shared__ uint32_t Bs[BK][BN + 4];   // [k][n]

    const int tid  = threadIdx.x;
    const int lane = tid & 31;
    const int wid  = tid >> 5;
    const int wm   = wid & 1;   // 2 warps along M
    const int wn   = wid >> 1;  // 4 warps along N

    const int bx = blockIdx.x, by = blockIdx.y;
    const float* Ablk = A + (long long)by * BM * K;
    const float* Bblk = Bm + bx * BN;

    float acc[4][4][4];
    #pragma unroll
    for (int i = 0; i < 4; i++)
        #pragma unroll
        for (int j = 0; j < 4; j++)
            #pragma unroll
            for (int q = 0; q < 4; q++) acc[i][j][q] = 0.0f;

    // A load mapping: 128 rows x 8 float4 (=32 k); 256 threads -> 4 rows each
    const int aR  = tid >> 3;         // base row 0..31
    const int aC4 = tid & 7;          // float4 index along k
    // B load mapping: 8 k-rows x 32 float4 per pass; 4 passes
    const int bR  = tid >> 5;         // 0..7
    const int bC4 = tid & 31;

    float4 aReg[4], bReg[4];

    auto load_tile = [&](int kt) {
        #pragma unroll
        for (int r = 0; r < 4; r++)
            aReg[r] = *(const float4*)(Ablk + (long long)(aR + r * 32) * K + kt + aC4 * 4);
        #pragma unroll
        for (int r = 0; r < 4; r++)
            bReg[r] = *(const float4*)(Bblk + (long long)(kt + bR + r * 8) * Nn + bC4 * 4);
    };
    auto store_tile = [&]() {
        #pragma unroll
        for (int r = 0; r < 4; r++) {
            int row = aR + r * 32;
            As[aC4 * 4 + 0][row] = f2tf32(aReg[r].x);
            As[aC4 * 4 + 1][row] = f2tf32(aReg[r].y);
            As[aC4 * 4 + 2][row] = f2tf32(aReg[r].z);
            As[aC4 * 4 + 3][row] = f2tf32(aReg[r].w);
        }
        #pragma unroll
        for (int r = 0; r < 4; r++) {
            int row = bR + r * 8;
            Bs[row][bC4 * 4 + 0] = f2tf32(bReg[r].x);
            Bs[row][bC4 * 4 + 1] = f2tf32(bReg[r].y);
            Bs[row][bC4 * 4 + 2] = f2tf32(bReg[r].z);
            Bs[row][bC4 * 4 + 3] = f2tf32(bReg[r].w);
        }
    };
    auto compute = [&]() {
        #pragma unroll
        for (int ks = 0; ks < BK; ks += 8) {
            uint32_t af[4][4];
            uint32_t bf[4][2];
            #pragma unroll
            for (int i = 0; i < 4; i++) {
                int mrow = wm * 64 + i * 16 + (lane >> 2);
                af[i][0] = As[ks + (lane & 3)    ][mrow];
                af[i][1] = As[ks + (lane & 3)    ][mrow + 8];
                af[i][2] = As[ks + (lane & 3) + 4][mrow];
                af[i][3] = As[ks + (lane & 3) + 4][mrow + 8];
            }
            #pragma unroll
            for (int j = 0; j < 4; j++) {
                int ncol = wn * 32 + j * 8 + (lane >> 2);
                bf[j][0] = Bs[ks + (lane & 3)    ][ncol];
                bf[j][1] = Bs[ks + (lane & 3) + 4][ncol];
            }
            #pragma unroll
            for (int i = 0; i < 4; i++)
                #pragma unroll
                for (int j = 0; j < 4; j++)
                    mma_tf32(acc[i][j], af[i][0], af[i][1], af[i][2], af[i][3],
                             bf[j][0], bf[j][1]);
        }
    };

    // Pipelined mainloop: prefetch next tile into regs while computing current
    load_tile(0);
    store_tile();
    __syncthreads();
    for (int kt = BK; kt < K; kt += BK) {
        load_tile(kt);        // LDGs in flight during compute below
        compute();
        __syncthreads();
        store_tile();
        __syncthreads();
    }
    compute();

    // Epilogue: c frag -> rows (lane>>2)+{0,8}, cols 2*(lane&3)+{0,1}
    float* Cblk = C + (long long)by * BM * Nn + bx * BN;
    #pragma unroll
    for (int i = 0; i < 4; i++) {
        #pragma unroll
        for (int j = 0; j < 4; j++) {
            int col = wn * 32 + j * 8 + 2 * (lane & 3);
            float bx0 = 0.0f, bx1 = 0.0f;
            if (bias) { bx0 = bias[bx * BN + col]; bx1 = bias[bx * BN + col + 1]; }
            #pragma unroll
            for (int h = 0; h < 2; h++) {
                int row = wm * 64 + i * 16 + (lane >> 2) + h * 8;
                float2 v;
                v.x = acc[i][j][h * 2 + 0] + bx0;
                v.y = acc[i][j][h * 2 + 1] + bx1;
                if (ACT == 1) {
                    v.x = v.x > 0.0f ? v.x : NEG_SLOPE * v.x;
                    v.y = v.y > 0.0f ? v.y : NEG_SLOPE * v.y;
                }
                *(float2*)(Cblk + (long long)row * Nn + col) = v;
            }
        }
    }
}

// ---------------------------------------------------------------------------
// Self-loop init: agg[n,:] = dinv[n]^2 * xw[n,:]
// ---------------------------------------------------------------------------
__global__ void selfloop_kernel() {
    int i = blockIdx.x * blockDim.x + threadIdx.x;
    if (i >= BNN * (F / 4)) return;
    int row = i / (F / 4);
    float d = g_dinv[row];
    float s = d * d;
    float4 v = ((const float4*)g_xw)[i];
    float4 o;
    o.x = s * v.x; o.y = s * v.y; o.z = s * v.z; o.w = s * v.w;
    ((float4*)g_agg)[i] = o;
}

// ---------------------------------------------------------------------------
// Edge scatter: one warp per edge, vector red.global.add.v4.f32
// (sm_103a arch feature; Round-1 trap was caused by garbage int64 indices,
//  not by the instruction)
// ---------------------------------------------------------------------------
__global__ __launch_bounds__(256)
void scatter_kernel(const int* __restrict__ ei) {
    int gw = (blockIdx.x * blockDim.x + threadIdx.x) >> 5;
    int lane = threadIdx.x & 31;
    if (gw >= B * E) return;
    int b = gw / E;
    int e = gw - b * E;
    const int* eb = ei + b * 2 * E;
    int src = eb[e];
    int dst = eb[E + e];
    float norm = g_dinv[b * NN + src] * g_dinv[b * NN + dst];
    const float4* s = (const float4*)(g_xw + (long long)(b * NN + src) * F);
    float4 v = s[lane];
    float4* d = ((float4*)(g_agg + (long long)(b * NN + dst) * F)) + lane;
    asm volatile("red.global.add.v4.f32 [%0], {%1,%2,%3,%4};"
                 :: "l"(d), "f"(v.x * norm), "f"(v.y * norm),
                    "f"(v.z * norm), "f"(v.w * norm)
                 : "memory");
}

// ---------------------------------------------------------------------------
// Post: out1 = relu(agg + bc) + x0   (written into g_xw, reused)
// ---------------------------------------------------------------------------
__global__ void post_kernel(const float* __restrict__ x0, const float* __restrict__ bc) {
    int i = blockIdx.x * blockDim.x + threadIdx.x;
    if (i >= BNN * (F / 4)) return;
    int c4 = i & (F / 4 - 1);
    float4 a = ((const float4*)g_agg)[i];
    float4 bb = ((const float4*)bc)[c4];
    float4 x = ((const float4*)x0)[i];
    float4 o;
    o.x = fmaxf(a.x + bb.x, 0.0f) + x.x;
    o.y = fmaxf(a.y + bb.y, 0.0f) + x.y;
    o.z = fmaxf(a.z + bb.z, 0.0f) + x.z;
    o.w = fmaxf(a.w + bb.w, 0.0f) + x.w;
    ((float4*)g_xw)[i] = o;
}

// ---------------------------------------------------------------------------
extern "C" void kernel_launch(void* const* d_in, const int* in_sizes, int n_in,
                              void* d_out, int out_size) {
    const float* x0 = (const float*)d_in[0];       // [B,N,F]
    const int*   ei = (const int*)d_in[1];         // [B,2,E] int32
    const float* Wc = (const float*)d_in[2];       // [F,F]
    const float* bc = (const float*)d_in[3];       // [F]
    const float* W1 = (const float*)d_in[4];       // [F,H]
    const float* b1 = (const float*)d_in[5];       // [H]
    const float* W2 = (const float*)d_in[6];       // [H,H]
    const float* b2 = (const float*)d_in[7];       // [H]
    float* out = (float*)d_out;                    // [B,N,H]

    float *xw, *agg, *h1;
    cudaGetSymbolAddress((void**)&xw,  g_xw);
    cudaGetSymbolAddress((void**)&agg, g_agg);
    cudaGetSymbolAddress((void**)&h1,  g_h1);

    // 1) degrees -> dinv
    init_deg_kernel<<<(BNN + 255) / 256, 256>>>();
    count_deg_kernel<<<(B * E + 255) / 256, 256>>>(ei);
    rsqrt_deg_kernel<<<(BNN + 255) / 256, 256>>>();

    // 2) xw = x0 @ Wc   (M=80000, N=128, K=128)
    {
        dim3 grid(F / BN, BNN / BM);
        tf32_gemm_kernel<0><<<grid, 256>>>(x0, Wc, nullptr, xw, BNN, F, F);
    }

    // 3) agg init with self loop, then edge scatter
    selfloop_kernel<<<(BNN * (F / 4) + 255) / 256, 256>>>();
    scatter_kernel<<<(B * E * 32 + 255) / 256, 256>>>(ei);

    // 4) out1 = relu(agg + bc) + x0  (into g_xw)
    post_kernel<<<(BNN * (F / 4) + 255) / 256, 256>>>(x0, bc);

    // 5) h1 = leaky_relu(out1 @ W1 + b1)  (M=80000, N=256, K=128)
    {
        dim3 grid(H / BN, BNN / BM);
        tf32_gemm_kernel<1><<<grid, 256>>>(xw, W1, b1, h1, BNN, H, F);
    }

    // 6) out = leaky_relu(h1 @ W2 + b2)  (M=80000, N=256, K=256)
    {
        dim3 grid(H / BN, BNN / BM);
        tf32_gemm_kernel<1><<<grid, 256>>>(h1, W2, b2, out, BNN, H, H);
    }
}